// round 11
// baseline (speedup 1.0000x reference)
#include <cuda_runtime.h>

// ============================================================================
// QPIE simulator v7: two-phase tree evaluation + PDL overlap.
//  Phase A: 16 (c0,c1) prefixes per batch evolve layers 0-1 once -> L2 state.
//  Phase B: 64 paths per batch, launched with ProgrammaticStreamSerialization:
//           blocks spin up DURING phaseA, build their own layer-2 tables in
//           smem (trig overlapped with phaseA), gridsync, then layer 2 +
//           sign-tracking Walsh measurement.
//  Layout per 4-warp group: qubits 0-4 = lanes, 5 = 2 regs, 6-7 = warp id.
// ============================================================================

struct Cplx { float re, im; };
__device__ __forceinline__ Cplx cmul(Cplx a, Cplx b) {
    return { a.re*b.re - a.im*b.im, a.re*b.im + a.im*b.re };
}
struct C2 { Cplx m[2][2]; };
__device__ __forceinline__ C2 c2mul(C2 A, C2 B) {
    C2 R;
#pragma unroll
    for (int i = 0; i < 2; i++)
#pragma unroll
        for (int j = 0; j < 2; j++) {
            Cplx s{0.f, 0.f};
#pragma unroll
            for (int k = 0; k < 2; k++) {
                Cplx p = cmul(A.m[i][k], B.m[k][j]);
                s.re += p.re; s.im += p.im;
            }
            R.m[i][j] = s;
        }
    return R;
}
__device__ __forceinline__ C2 mRX(float t) {
    float s, c; sincosf(0.5f*t, &s, &c);
    return C2{{{{c,0.f},{0.f,-s}},{{0.f,-s},{c,0.f}}}};
}
__device__ __forceinline__ C2 mRY(float t) {
    float s, c; sincosf(0.5f*t, &s, &c);
    return C2{{{{c,0.f},{-s,0.f}},{{s,0.f},{c,0.f}}}};
}
__device__ __forceinline__ C2 mRZ(float t) {
    float s, c; sincosf(0.5f*t, &s, &c);
    return C2{{{{c,-s},{0.f,0.f}},{{0.f,0.f},{c,s}}}};
}

// prefix states: [batch*16+prefix][W][reg][lane] as float2
__device__ float2 g_state[512 * 256];

// ---- table builders ----
__device__ __forceinline__ void make_tail(float4* dst, const float* wl, int q,
                                          int rotType, float xv) {
    C2 V = c2mul(mRZ(wl[26 + 3*q]), c2mul(mRY(wl[25 + 3*q]), mRX(wl[24 + 3*q])));
    if (rotType == 1)      V = c2mul(mRX(xv), V);
    else if (rotType == 2) V = c2mul(mRY(xv), V);
    dst[0] = make_float4(V.m[0][0].re, V.m[0][0].im, V.m[0][1].re, V.m[0][1].im);
    dst[1] = make_float4(V.m[1][0].re, V.m[1][0].im, V.m[1][1].re, V.m[1][1].im);
}
__device__ __forceinline__ void make_cf(float* o, const float* wl3) {
    float tx = wl3[0], ty = wl3[1], tz = wl3[2];
    float sd, cd, ss, cs, sz, cz;
    sincosf(0.5f*(tx - ty), &sd, &cd);
    sincosf(0.5f*(tx + ty), &ss, &cs);
    sincosf(0.5f*tz,        &sz, &cz);
    o[0]=cd; o[1]=sd; o[2]=cs; o[3]=ss; o[4]=cz; o[5]=sz;
}

// ---- gate primitives (2 register slots per thread) ----
template<int Q>
__device__ __forceinline__ void sq_lane(float (&vre)[2], float (&vim)[2], unsigned lane,
                                        Cplx u00, Cplx u01, Cplx u10, Cplx u11) {
    constexpr int m = 1 << Q;
    const bool hi = (lane & m) != 0;
    const Cplx a = hi ? u11 : u00;
    const Cplx b = hi ? u10 : u01;
#pragma unroll
    for (int r = 0; r < 2; r++) {
        float ore = __shfl_xor_sync(0xffffffffu, vre[r], m);
        float oim = __shfl_xor_sync(0xffffffffu, vim[r], m);
        float wre = vre[r], wim = vim[r];
        vre[r] = a.re*wre - a.im*wim + b.re*ore - b.im*oim;
        vim[r] = a.re*wim + a.im*wre + b.re*oim + b.im*ore;
    }
}
__device__ __forceinline__ void sq_reg(float (&vre)[2], float (&vim)[2],
                                       Cplx u00, Cplx u01, Cplx u10, Cplx u11) {
    float v0r = vre[0], v0i = vim[0], v1r = vre[1], v1i = vim[1];
    vre[0] = u00.re*v0r - u00.im*v0i + u01.re*v1r - u01.im*v1i;
    vim[0] = u00.re*v0i + u00.im*v0r + u01.re*v1i + u01.im*v1r;
    vre[1] = u10.re*v0r - u10.im*v0i + u11.re*v1r - u11.im*v1i;
    vim[1] = u10.re*v0i + u10.im*v0r + u11.re*v1i + u11.im*v1r;
}
__device__ __forceinline__ void ent_step(float& vr, float& vi, float wr, float wi, int p,
                                         float cd, float sd, float cs, float ss,
                                         float cz, float sz) {
    const float c = p ? cs : cd, s = p ? ss : sd, phim = p ? sz : -sz;
    float tre = c*vr + s*wi;
    float tim = c*vi - s*wr;
    vr = cz*tre - phim*tim;
    vi = cz*tim + phim*tre;
}
template<int Q1, int Q2>
__device__ __forceinline__ void ent_ll(float (&vre)[2], float (&vim)[2], unsigned lane,
                                       const float* __restrict__ cf) {
    const float cd = cf[0], sd = cf[1], cs = cf[2], ss = cf[3], cz = cf[4], sz = cf[5];
    constexpr int lm = (1 << Q1) | (1 << Q2);
    const int p = (int)(((lane >> Q1) ^ (lane >> Q2)) & 1u);
#pragma unroll
    for (int r = 0; r < 2; r++) {
        float wr = __shfl_xor_sync(0xffffffffu, vre[r], lm);
        float wi = __shfl_xor_sync(0xffffffffu, vim[r], lm);
        ent_step(vre[r], vim[r], wr, wi, p, cd, sd, cs, ss, cz, sz);
    }
}
__device__ __forceinline__ void ent_45(float (&vre)[2], float (&vim)[2], unsigned lane,
                                       const float* __restrict__ cf) {
    const float cd = cf[0], sd = cf[1], cs = cf[2], ss = cf[3], cz = cf[4], sz = cf[5];
    const int l4 = (int)((lane >> 4) & 1u);
    float w0r = __shfl_xor_sync(0xffffffffu, vre[1], 16);
    float w0i = __shfl_xor_sync(0xffffffffu, vim[1], 16);
    float w1r = __shfl_xor_sync(0xffffffffu, vre[0], 16);
    float w1i = __shfl_xor_sync(0xffffffffu, vim[0], 16);
    ent_step(vre[0], vim[0], w0r, w0i, l4 ^ 0, cd, sd, cs, ss, cz, sz);
    ent_step(vre[1], vim[1], w1r, w1i, l4 ^ 1, cd, sd, cs, ss, cz, sz);
}
template<int QC, int QT>
__device__ __forceinline__ void crx_ll(float (&vre)[2], float (&vim)[2], unsigned lane) {
    const float c = 0.92387953251128674f;
    const float s = 0.38268343236508977f;
    constexpr int m = 1 << QT;
    const bool ctrl = ((lane >> QC) & 1u) != 0;
#pragma unroll
    for (int r = 0; r < 2; r++) {
        float wr = __shfl_xor_sync(0xffffffffu, vre[r], m);
        float wi = __shfl_xor_sync(0xffffffffu, vim[r], m);
        if (ctrl) {
            float nr = c*vre[r] + s*wi;
            float ni = c*vim[r] - s*wr;
            vre[r] = nr; vim[r] = ni;
        }
    }
}

// on-the-fly ancilla branch factor
__device__ __forceinline__ void branch_mul(float (&vre)[2], float (&vim)[2],
                                           const float* __restrict__ sPW, unsigned lane,
                                           int w0, int w1, int r0, int r1, bool even) {
    float sl0 = 0.f, sl1 = 0.f;
#pragma unroll
    for (int j = 0; j < 5; j++) {
        float b = (float)((lane >> j) & 1u);
        sl0 += b * sPW[j];
        sl1 += b * sPW[8 + j];
    }
    if (w0) { sl0 += sPW[6];  sl1 += sPW[14]; }
    if (w1) { sl0 += sPW[7];  sl1 += sPW[15]; }
#pragma unroll
    for (int r = 0; r < 2; r++) {
        float s0 = sl0 + (r ? sPW[5]  : 0.f);
        float s1 = sl1 + (r ? sPW[13] : 0.f);
        float sn0, cn0, sn1, cn1;
        __sincosf(0.5f*s0, &sn0, &cn0);
        __sincosf(0.5f*s1, &sn1, &cn1);
        Cplx a, b;
        if (even) {
            const float k = 0.70710678118654752f;
            a = { k*cn0, r0 ? k*sn0 : -k*sn0 };
            b = { k*cn1, r1 ? k*sn1 : -k*sn1 };
        } else {
            a = r0 ? Cplx{0.f, -sn0} : Cplx{cn0, 0.f};
            b = r1 ? Cplx{0.f, -sn1} : Cplx{cn1, 0.f};
        }
        Cplx g = cmul(a, b);
        float wr = vre[r], wi = vim[r];
        vre[r] = g.re*wr - g.im*wi;
        vim[r] = g.re*wi + g.im*wr;
    }
}

template<bool NAMED>
__device__ __forceinline__ void grp_barrier(int id) {
    if constexpr (NAMED) asm volatile("bar.sync %0, 128;" :: "r"(id) : "memory");
    else __syncthreads();
}

// full entangler + single-qubit-tail section for one layer
template<bool NAMED>
__device__ __forceinline__ void layer_gates(float (&vre)[2], float (&vim)[2], unsigned lane,
                                            int W, int w0, int w1, int r0, int r1,
                                            const float* __restrict__ cf,
                                            const float4* __restrict__ M,
                                            float2* exg, int barId, int& xc) {
    ent_ll<0,1>(vre, vim, lane, cf + 0);
    if (r0) crx_ll<0,1>(vre, vim, lane);
    ent_ll<2,3>(vre, vim, lane, cf + 6);
    if (r1) crx_ll<2,3>(vre, vim, lane);
    ent_45(vre, vim, lane, cf + 12);

    // (6,7): partner warp W^3, parity w0^w1
    {
        const float* c6 = cf + 18;
        float2* b = exg + (xc & 1) * 256; xc++;
        b[W*64 + lane]      = make_float2(vre[0], vim[0]);
        b[W*64 + 32 + lane] = make_float2(vre[1], vim[1]);
        grp_barrier<NAMED>(barId);
        float2 p0 = b[(W^3)*64 + lane];
        float2 p1 = b[(W^3)*64 + 32 + lane];
        const int p = w0 ^ w1;
        ent_step(vre[0], vim[0], p0.x, p0.y, p, c6[0], c6[1], c6[2], c6[3], c6[4], c6[5]);
        ent_step(vre[1], vim[1], p1.x, p1.y, p, c6[0], c6[1], c6[2], c6[3], c6[4], c6[5]);
    }

    ent_ll<1,2>(vre, vim, lane, cf + 24);
    ent_ll<3,4>(vre, vim, lane, cf + 30);

    // (5,6): partner warp W^1, opposite reg, parity r^w0
    {
        const float* c5 = cf + 36;
        float2* b = exg + (xc & 1) * 256; xc++;
        b[W*64 + lane]      = make_float2(vre[0], vim[0]);
        b[W*64 + 32 + lane] = make_float2(vre[1], vim[1]);
        grp_barrier<NAMED>(barId);
        float2 p0 = b[(W^1)*64 + 32 + lane];
        float2 p1 = b[(W^1)*64 + lane];
        ent_step(vre[0], vim[0], p0.x, p0.y, 0 ^ w0, c5[0], c5[1], c5[2], c5[3], c5[4], c5[5]);
        ent_step(vre[1], vim[1], p1.x, p1.y, 1 ^ w0, c5[0], c5[1], c5[2], c5[3], c5[4], c5[5]);
    }

    // single-qubit tail: qubits 0-4 lanes, 5 reg
    {
        float4 a, b4;
        a = M[0];  b4 = M[1];
        sq_lane<0>(vre, vim, lane, Cplx{a.x,a.y}, Cplx{a.z,a.w}, Cplx{b4.x,b4.y}, Cplx{b4.z,b4.w});
        a = M[2];  b4 = M[3];
        sq_lane<1>(vre, vim, lane, Cplx{a.x,a.y}, Cplx{a.z,a.w}, Cplx{b4.x,b4.y}, Cplx{b4.z,b4.w});
        a = M[4];  b4 = M[5];
        sq_lane<2>(vre, vim, lane, Cplx{a.x,a.y}, Cplx{a.z,a.w}, Cplx{b4.x,b4.y}, Cplx{b4.z,b4.w});
        a = M[6];  b4 = M[7];
        sq_lane<3>(vre, vim, lane, Cplx{a.x,a.y}, Cplx{a.z,a.w}, Cplx{b4.x,b4.y}, Cplx{b4.z,b4.w});
        a = M[8];  b4 = M[9];
        sq_lane<4>(vre, vim, lane, Cplx{a.x,a.y}, Cplx{a.z,a.w}, Cplx{b4.x,b4.y}, Cplx{b4.z,b4.w});
        a = M[10]; b4 = M[11];
        sq_reg(vre, vim, Cplx{a.x,a.y}, Cplx{a.z,a.w}, Cplx{b4.x,b4.y}, Cplx{b4.z,b4.w});
    }
    // fused U6 (x) U7 on warp qubits: one exchange, 4x4 apply
    {
        float4 r6 = M[12 + w0];
        float4 r7 = M[14 + w1];
        Cplx u6[2] = { {r6.x, r6.y}, {r6.z, r6.w} };
        Cplx u7[2] = { {r7.x, r7.y}, {r7.z, r7.w} };
        Cplx cc[4];
#pragma unroll
        for (int Wp = 0; Wp < 4; Wp++) cc[Wp] = cmul(u7[Wp >> 1], u6[Wp & 1]);
        float2* b = exg + (xc & 1) * 256; xc++;
        b[W*64 + lane]      = make_float2(vre[0], vim[0]);
        b[W*64 + 32 + lane] = make_float2(vre[1], vim[1]);
        grp_barrier<NAMED>(barId);
#pragma unroll
        for (int r = 0; r < 2; r++) {
            float ar = 0.f, ai = 0.f;
#pragma unroll
            for (int Wp = 0; Wp < 4; Wp++) {
                float2 v = b[Wp*64 + r*32 + lane];
                ar += cc[Wp].re*v.x - cc[Wp].im*v.y;
                ai += cc[Wp].re*v.y + cc[Wp].im*v.x;
            }
            vre[r] = ar; vim[r] = ai;
        }
    }
}

// ---------------- Phase A: layers 0-1 for 16 prefixes/batch ----------------
__global__ void __launch_bounds__(256)
qpie_phaseA(const float* __restrict__ x, const float* __restrict__ w,
            const float* __restrict__ pw, float* __restrict__ out, int out_n) {
    // Let phaseB launch immediately (it builds its own tables during overlap).
#if __CUDA_ARCH__ >= 900
    if (threadIdx.x == 0) cudaTriggerProgrammaticLaunchCompletion();
#endif
    const int tid = threadIdx.x;
    const unsigned lane = tid & 31u;
    const int wib = tid >> 5;
    const int grp = wib >> 2;
    const int W   = wib & 3;
    const int w0 = W & 1, w1 = W >> 1;
    const int batch = blockIdx.x >> 3;
    const int pf = ((blockIdx.x & 7) << 1) | grp;   // 0..15
    const int c0 = pf & 3, c1 = (pf >> 2) & 3;
    const int barId = grp + 1;

    __shared__ float4 sM[2][16];
    __shared__ float  sCF[2][42];
    __shared__ float2 sInit[8];
    __shared__ float  sPW[32];
    __shared__ float2 sEx[2][512];

    if (blockIdx.x == 0)
        for (int i = tid; i < out_n; i += 256) out[i] = 0.f;

    if (tid < 16) {
        int l = tid >> 3, q = tid & 7;
        make_tail(&sM[l][q*2], w + l*48, q, (l == 0) ? 1 : 2, x[batch*8 + q]);
    } else if (tid >= 32 && tid < 46) {
        int i = tid - 32, l = i / 7, p = i % 7;
        make_cf(&sCF[l][p*6], w + l*48 + 3*p);
    } else if (tid >= 64 && tid < 72) {
        int q = tid - 64;
        float s, c; sincosf(0.5f * x[batch*8 + q], &s, &c);
        sInit[q] = make_float2(c - s, c + s);
    } else if (tid >= 96 && tid < 128) {
        sPW[tid - 96] = pw[tid - 96];
    }
    __syncthreads();

    // initial product state (H then RY(x))|0>, 1/sqrt2^8 deferred
    float vre[2], vim[2];
    {
        float base = 1.f;
#pragma unroll
        for (int q = 0; q < 5; q++) base *= ((lane >> q) & 1u) ? sInit[q].y : sInit[q].x;
        base *= w0 ? sInit[6].y : sInit[6].x;
        base *= w1 ? sInit[7].y : sInit[7].x;
        vre[0] = base * sInit[5].x; vim[0] = 0.f;
        vre[1] = base * sInit[5].y; vim[1] = 0.f;
    }

    int xc = 0;
    // layer 0 (even)
    branch_mul(vre, vim, &sPW[0], lane, w0, w1, c0 & 1, (c0 >> 1) & 1, true);
    layer_gates<true>(vre, vim, lane, W, w0, w1, c0 & 1, (c0 >> 1) & 1,
                      sCF[0], sM[0], &sEx[grp][0], barId, xc);
    // layer 1 (odd)
    branch_mul(vre, vim, &sPW[16], lane, w0, w1, c1 & 1, (c1 >> 1) & 1, false);
    layer_gates<true>(vre, vim, lane, W, w0, w1, c1 & 1, (c1 >> 1) & 1,
                      sCF[1], sM[1], &sEx[grp][0], barId, xc);

    const int gidx = batch * 16 + pf;
    const int base = (gidx * 4 + W) * 64 + (int)lane;
    g_state[base]      = make_float2(vre[0], vim[0]);
    g_state[base + 32] = make_float2(vre[1], vim[1]);
}

// ---------------- Phase B: layer 2 + measurement, 64 paths/batch ----------------
__global__ void __launch_bounds__(128)
qpie_phaseB(const float* __restrict__ w, const float* __restrict__ pw,
            float* __restrict__ out) {
    const int tid = threadIdx.x;
    const unsigned lane = tid & 31u;
    const int W = tid >> 5;
    const int w0 = W & 1, w1 = W >> 1;
    const int batch = blockIdx.x >> 6;
    const int path  = blockIdx.x & 63;
    const int pf = path & 15, c2 = path >> 4;
    const int r0 = c2 & 1, r1 = (c2 >> 1) & 1;

    __shared__ float4 sM[16];
    __shared__ float  sCF[42];
    __shared__ float  sPW[16];
    __shared__ float2 sEx[512];
    __shared__ float  sOut[8];

    // Build own tables during the PDL overlap window (w/pw are kernel inputs,
    // independent of phaseA) -- this trig is off the critical path.
    if (tid < 8) {
        make_tail(&sM[tid*2], w + 96, tid, 0, 0.f);
        sOut[tid] = 0.f;
    } else if (tid >= 16 && tid < 23) {
        make_cf(&sCF[(tid - 16)*6], w + 96 + 3*(tid - 16));
    } else if (tid >= 32 && tid < 48) {
        sPW[tid - 32] = pw[32 + (tid - 32)];
    }
    __syncthreads();

    // Wait for phaseA's g_state writes to be visible.
#if __CUDA_ARCH__ >= 900
    cudaGridDependencySynchronize();
#endif

    // load prefix state
    float vre[2], vim[2];
    {
        const int base = ((batch*16 + pf) * 4 + W) * 64 + (int)lane;
        float2 v0 = g_state[base], v1 = g_state[base + 32];
        vre[0] = v0.x; vim[0] = v0.y;
        vre[1] = v1.x; vim[1] = v1.y;
    }
    // layer 2 (even)
    branch_mul(vre, vim, sPW, lane, w0, w1, r0, r1, true);
    int xc = 0;
    layer_gates<false>(vre, vim, lane, W, w0, w1, r0, r1, sCF, sM, sEx, 0, xc);

    // ---- measurement: sign-tracking Walsh butterfly ----
    float p0 = vre[0]*vre[0] + vim[0]*vim[0];
    float p1 = vre[1]*vre[1] + vim[1]*vim[1];
    float A = p0 + p1, B = p0 - p1;
    float S[5];
#pragma unroll
    for (int k = 0; k < 5; k++) {
        const int mk = 1 << k;
        float Ap = __shfl_xor_sync(0xffffffffu, A, mk);
#pragma unroll
        for (int q = 0; q < 5; q++) {
            if (q < k) S[q] += __shfl_xor_sync(0xffffffffu, S[q], mk);
        }
        S[k] = ((lane >> k) & 1u) ? (Ap - A) : (A - Ap);
        A += Ap;
        B += __shfl_xor_sync(0xffffffffu, B, mk);
    }
    float v = S[0];
    if (lane == 1) v = S[1];
    else if (lane == 2) v = S[2];
    else if (lane == 3) v = S[3];
    else if (lane == 4) v = S[4];
    else if (lane == 5) v = B;
    else if (lane == 6) v = w0 ? -A : A;
    else if (lane == 7) v = w1 ? -A : A;
    if (lane < 8) atomicAdd(&sOut[lane], v);
    __syncthreads();
    if (tid < 8)
        atomicAdd(&out[batch*8 + tid], sOut[tid] * (1.f/256.f));
}

extern "C" void kernel_launch(void* const* d_in, const int* in_sizes, int n_in,
                              void* d_out, int out_size) {
    const float* x  = (const float*)d_in[0];   // [B, 8]
    const float* w  = (const float*)d_in[1];   // [3, 48]
    const float* pw = (const float*)d_in[2];   // [3, 2, 8]
    float* out = (float*)d_out;

    const int nb = in_sizes[0] / 8;            // 16
    qpie_phaseA<<<nb * 8, 256>>>(x, w, pw, out, out_size);

    // phaseB with Programmatic Stream Serialization: launches during phaseA,
    // builds tables, gridsyncs, then consumes g_state with no launch gap.
    cudaLaunchConfig_t cfg = {};
    cfg.gridDim  = dim3(nb * 64, 1, 1);
    cfg.blockDim = dim3(128, 1, 1);
    cudaLaunchAttribute attrs[1];
    attrs[0].id = cudaLaunchAttributeProgrammaticStreamSerialization;
    attrs[0].val.programmaticStreamSerializationAllowed = 1;
    cfg.attrs = attrs;
    cfg.numAttrs = 1;
    cudaLaunchKernelEx(&cfg, qpie_phaseB, w, pw, out);
}

// round 12
// speedup vs baseline: 1.1404x; 1.1404x over previous
#include <cuda_runtime.h>

// ============================================================================
// QPIE simulator v8: two-phase tree evaluation, single-exchange layer tail.
//  The (5,6),(6,7) entanglers + U5,U6,U7 rotations collapse into ONE 8x8
//  complex matrix T on the reg/warp qubits -> one smem exchange per layer
//  (was three). T is built per-block from smem tables; phaseA block 0
//  prebuilds phaseB's layer-2 tables (incl. T2) into globals.
//  Layout per 4-warp group: qubits 0-4 = lanes, 5 = 2 regs, 6-7 = warp id.
// ============================================================================

struct Cplx { float re, im; };
__device__ __forceinline__ Cplx cmul(Cplx a, Cplx b) {
    return { a.re*b.re - a.im*b.im, a.re*b.im + a.im*b.re };
}
struct C2 { Cplx m[2][2]; };
__device__ __forceinline__ C2 c2mul(C2 A, C2 B) {
    C2 R;
#pragma unroll
    for (int i = 0; i < 2; i++)
#pragma unroll
        for (int j = 0; j < 2; j++) {
            Cplx s{0.f, 0.f};
#pragma unroll
            for (int k = 0; k < 2; k++) {
                Cplx p = cmul(A.m[i][k], B.m[k][j]);
                s.re += p.re; s.im += p.im;
            }
            R.m[i][j] = s;
        }
    return R;
}
__device__ __forceinline__ C2 mRX(float t) {
    float s, c; sincosf(0.5f*t, &s, &c);
    return C2{{{{c,0.f},{0.f,-s}},{{0.f,-s},{c,0.f}}}};
}
__device__ __forceinline__ C2 mRY(float t) {
    float s, c; sincosf(0.5f*t, &s, &c);
    return C2{{{{c,0.f},{-s,0.f}},{{s,0.f},{c,0.f}}}};
}
__device__ __forceinline__ C2 mRZ(float t) {
    float s, c; sincosf(0.5f*t, &s, &c);
    return C2{{{{c,-s},{0.f,0.f}},{{0.f,0.f},{c,s}}}};
}

// prefix states: [batch*16+prefix][W][reg][lane] as float2
__device__ float2 g_state[512 * 256];
// phaseB layer-2 tables (built once by phaseA block 0)
__device__ float2 g_T2[64];
__device__ float4 g_M2[10];
__device__ float  g_CF2[42];
__device__ float  g_PW2[16];

// ---- table builders ----
__device__ __forceinline__ void make_tail(float4* dst, const float* wl, int q,
                                          int rotType, float xv) {
    C2 V = c2mul(mRZ(wl[26 + 3*q]), c2mul(mRY(wl[25 + 3*q]), mRX(wl[24 + 3*q])));
    if (rotType == 1)      V = c2mul(mRX(xv), V);
    else if (rotType == 2) V = c2mul(mRY(xv), V);
    dst[0] = make_float4(V.m[0][0].re, V.m[0][0].im, V.m[0][1].re, V.m[0][1].im);
    dst[1] = make_float4(V.m[1][0].re, V.m[1][0].im, V.m[1][1].re, V.m[1][1].im);
}
__device__ __forceinline__ void make_cf(float* o, const float* wl3) {
    float tx = wl3[0], ty = wl3[1], tz = wl3[2];
    float sd, cd, ss, cs, sz, cz;
    sincosf(0.5f*(tx - ty), &sd, &cd);
    sincosf(0.5f*(tx + ty), &ss, &cs);
    sincosf(0.5f*tz,        &sz, &cz);
    o[0]=cd; o[1]=sd; o[2]=cs; o[3]=ss; o[4]=cz; o[5]=sz;
}

// Entangler 8x8 matrix element on the (q5,q6,q7) subspace.
// row couples to row^flip; parity p selects coeffs; cf = {cd,sd,cs,ss,cz,sz}.
__device__ __forceinline__ Cplx e_entry(int row, int col, int flip, int p,
                                        const float* cf) {
    float c    = p ? cf[2] : cf[0];
    float s    = p ? cf[3] : cf[1];
    float phim = p ? cf[5] : -cf[5];
    Cplx ph{cf[4], phim};
    if (col == row)          return cmul(ph, Cplx{c, 0.f});
    if (col == (row ^ flip)) return cmul(ph, Cplx{0.f, -s});
    return Cplx{0.f, 0.f};
}

// T = (U5 (x) U6 (x) U7) * E56 * E67, entry e = r*8+c.
// idx bits: b0 = q5(reg), b1 = q6(w0), b2 = q7(w1).
__device__ float2 T_entry(int e, const float4* sMl, const float* cfL) {
    const float* cf67 = cfL + 18;   // pair (6,7)
    const float* cf56 = cfL + 36;   // pair (5,6)
    int r = e >> 3, c = e & 7;
    Cplx acc{0.f, 0.f};
#pragma unroll
    for (int k = 0; k < 8; k++) {
        // P[k][c] = sum_{j in {k, k^3}} E56[k][j] * E67[j][c]
        Cplx P{0.f, 0.f};
#pragma unroll
        for (int jj = 0; jj < 2; jj++) {
            int j = jj ? (k ^ 3) : k;
            Cplx a = e_entry(k, j, 3, (k ^ (k >> 1)) & 1, cf56);
            Cplx b = e_entry(j, c, 6, ((j >> 1) ^ (j >> 2)) & 1, cf67);
            Cplx pr = cmul(a, b);
            P.re += pr.re; P.im += pr.im;
        }
        float4 m5 = sMl[10 + (r & 1)];
        Cplx u5 = (k & 1) ? Cplx{m5.z, m5.w} : Cplx{m5.x, m5.y};
        float4 m6 = sMl[12 + ((r >> 1) & 1)];
        Cplx u6 = ((k >> 1) & 1) ? Cplx{m6.z, m6.w} : Cplx{m6.x, m6.y};
        float4 m7 = sMl[14 + (r >> 2)];
        Cplx u7 = (k >> 2) ? Cplx{m7.z, m7.w} : Cplx{m7.x, m7.y};
        Cplx t = cmul(cmul(cmul(u5, u6), u7), P);
        acc.re += t.re; acc.im += t.im;
    }
    return make_float2(acc.re, acc.im);
}

// ---- gate primitives (2 register slots per thread) ----
template<int Q>
__device__ __forceinline__ void sq_lane(float (&vre)[2], float (&vim)[2], unsigned lane,
                                        Cplx u00, Cplx u01, Cplx u10, Cplx u11) {
    constexpr int m = 1 << Q;
    const bool hi = (lane & m) != 0;
    const Cplx a = hi ? u11 : u00;
    const Cplx b = hi ? u10 : u01;
#pragma unroll
    for (int r = 0; r < 2; r++) {
        float ore = __shfl_xor_sync(0xffffffffu, vre[r], m);
        float oim = __shfl_xor_sync(0xffffffffu, vim[r], m);
        float wre = vre[r], wim = vim[r];
        vre[r] = a.re*wre - a.im*wim + b.re*ore - b.im*oim;
        vim[r] = a.re*wim + a.im*wre + b.re*oim + b.im*ore;
    }
}
__device__ __forceinline__ void ent_step(float& vr, float& vi, float wr, float wi, int p,
                                         float cd, float sd, float cs, float ss,
                                         float cz, float sz) {
    const float c = p ? cs : cd, s = p ? ss : sd, phim = p ? sz : -sz;
    float tre = c*vr + s*wi;
    float tim = c*vi - s*wr;
    vr = cz*tre - phim*tim;
    vi = cz*tim + phim*tre;
}
template<int Q1, int Q2>
__device__ __forceinline__ void ent_ll(float (&vre)[2], float (&vim)[2], unsigned lane,
                                       const float* __restrict__ cf) {
    const float cd = cf[0], sd = cf[1], cs = cf[2], ss = cf[3], cz = cf[4], sz = cf[5];
    constexpr int lm = (1 << Q1) | (1 << Q2);
    const int p = (int)(((lane >> Q1) ^ (lane >> Q2)) & 1u);
#pragma unroll
    for (int r = 0; r < 2; r++) {
        float wr = __shfl_xor_sync(0xffffffffu, vre[r], lm);
        float wi = __shfl_xor_sync(0xffffffffu, vim[r], lm);
        ent_step(vre[r], vim[r], wr, wi, p, cd, sd, cs, ss, cz, sz);
    }
}
__device__ __forceinline__ void ent_45(float (&vre)[2], float (&vim)[2], unsigned lane,
                                       const float* __restrict__ cf) {
    const float cd = cf[0], sd = cf[1], cs = cf[2], ss = cf[3], cz = cf[4], sz = cf[5];
    const int l4 = (int)((lane >> 4) & 1u);
    float w0r = __shfl_xor_sync(0xffffffffu, vre[1], 16);
    float w0i = __shfl_xor_sync(0xffffffffu, vim[1], 16);
    float w1r = __shfl_xor_sync(0xffffffffu, vre[0], 16);
    float w1i = __shfl_xor_sync(0xffffffffu, vim[0], 16);
    ent_step(vre[0], vim[0], w0r, w0i, l4 ^ 0, cd, sd, cs, ss, cz, sz);
    ent_step(vre[1], vim[1], w1r, w1i, l4 ^ 1, cd, sd, cs, ss, cz, sz);
}
template<int QC, int QT>
__device__ __forceinline__ void crx_ll(float (&vre)[2], float (&vim)[2], unsigned lane) {
    const float c = 0.92387953251128674f;
    const float s = 0.38268343236508977f;
    constexpr int m = 1 << QT;
    const bool ctrl = ((lane >> QC) & 1u) != 0;
#pragma unroll
    for (int r = 0; r < 2; r++) {
        float wr = __shfl_xor_sync(0xffffffffu, vre[r], m);
        float wi = __shfl_xor_sync(0xffffffffu, vim[r], m);
        if (ctrl) {
            float nr = c*vre[r] + s*wi;
            float ni = c*vim[r] - s*wr;
            vre[r] = nr; vim[r] = ni;
        }
    }
}

// on-the-fly ancilla branch factor
__device__ __forceinline__ void branch_mul(float (&vre)[2], float (&vim)[2],
                                           const float* __restrict__ sPW, unsigned lane,
                                           int w0, int w1, int r0, int r1, bool even) {
    float sl0 = 0.f, sl1 = 0.f;
#pragma unroll
    for (int j = 0; j < 5; j++) {
        float b = (float)((lane >> j) & 1u);
        sl0 += b * sPW[j];
        sl1 += b * sPW[8 + j];
    }
    if (w0) { sl0 += sPW[6];  sl1 += sPW[14]; }
    if (w1) { sl0 += sPW[7];  sl1 += sPW[15]; }
#pragma unroll
    for (int r = 0; r < 2; r++) {
        float s0 = sl0 + (r ? sPW[5]  : 0.f);
        float s1 = sl1 + (r ? sPW[13] : 0.f);
        float sn0, cn0, sn1, cn1;
        __sincosf(0.5f*s0, &sn0, &cn0);
        __sincosf(0.5f*s1, &sn1, &cn1);
        Cplx a, b;
        if (even) {
            const float k = 0.70710678118654752f;
            a = { k*cn0, r0 ? k*sn0 : -k*sn0 };
            b = { k*cn1, r1 ? k*sn1 : -k*sn1 };
        } else {
            a = r0 ? Cplx{0.f, -sn0} : Cplx{cn0, 0.f};
            b = r1 ? Cplx{0.f, -sn1} : Cplx{cn1, 0.f};
        }
        Cplx g = cmul(a, b);
        float wr = vre[r], wi = vim[r];
        vre[r] = g.re*wr - g.im*wi;
        vim[r] = g.re*wi + g.im*wr;
    }
}

template<bool NAMED>
__device__ __forceinline__ void grp_barrier(int id) {
    if constexpr (NAMED) asm volatile("bar.sync %0, 128;" :: "r"(id) : "memory");
    else __syncthreads();
}

// Single exchange + 8x8 T on qubits (5,6,7). exb = 8 slots x 32 lanes.
template<bool NAMED>
__device__ __forceinline__ void apply_T(float (&vre)[2], float (&vim)[2], unsigned lane,
                                        int W, const float2* __restrict__ sT,
                                        float2* exb, int barId) {
    exb[(2*W)*32 + lane]     = make_float2(vre[0], vim[0]);
    exb[(2*W + 1)*32 + lane] = make_float2(vre[1], vim[1]);
    grp_barrier<NAMED>(barId);
    float2 in[8];
#pragma unroll
    for (int c = 0; c < 8; c++) in[c] = exb[c*32 + lane];
#pragma unroll
    for (int r = 0; r < 2; r++) {
        const float2* row = sT + (2*W + r)*8;
        float ar = 0.f, ai = 0.f;
#pragma unroll
        for (int c = 0; c < 8; c++) {
            float2 t = row[c]; float2 v = in[c];
            ar = fmaf(t.x, v.x, fmaf(-t.y, v.y, ar));
            ai = fmaf(t.x, v.y, fmaf(t.y, v.x, ai));
        }
        vre[r] = ar; vim[r] = ai;
    }
}

// full layer: lane entanglers + lane rotations + one-exchange 8x8 tail
template<bool NAMED>
__device__ __forceinline__ void layer_gates(float (&vre)[2], float (&vim)[2], unsigned lane,
                                            int W, int r0, int r1,
                                            const float* __restrict__ cf,
                                            const float4* __restrict__ M,
                                            const float2* __restrict__ sT,
                                            float2* exb, int barId) {
    ent_ll<0,1>(vre, vim, lane, cf + 0);
    if (r0) crx_ll<0,1>(vre, vim, lane);
    ent_ll<2,3>(vre, vim, lane, cf + 6);
    if (r1) crx_ll<2,3>(vre, vim, lane);
    ent_45(vre, vim, lane, cf + 12);
    ent_ll<1,2>(vre, vim, lane, cf + 24);
    ent_ll<3,4>(vre, vim, lane, cf + 30);

    float4 a, b4;
    a = M[0];  b4 = M[1];
    sq_lane<0>(vre, vim, lane, Cplx{a.x,a.y}, Cplx{a.z,a.w}, Cplx{b4.x,b4.y}, Cplx{b4.z,b4.w});
    a = M[2];  b4 = M[3];
    sq_lane<1>(vre, vim, lane, Cplx{a.x,a.y}, Cplx{a.z,a.w}, Cplx{b4.x,b4.y}, Cplx{b4.z,b4.w});
    a = M[4];  b4 = M[5];
    sq_lane<2>(vre, vim, lane, Cplx{a.x,a.y}, Cplx{a.z,a.w}, Cplx{b4.x,b4.y}, Cplx{b4.z,b4.w});
    a = M[6];  b4 = M[7];
    sq_lane<3>(vre, vim, lane, Cplx{a.x,a.y}, Cplx{a.z,a.w}, Cplx{b4.x,b4.y}, Cplx{b4.z,b4.w});
    a = M[8];  b4 = M[9];
    sq_lane<4>(vre, vim, lane, Cplx{a.x,a.y}, Cplx{a.z,a.w}, Cplx{b4.x,b4.y}, Cplx{b4.z,b4.w});

    apply_T<NAMED>(vre, vim, lane, W, sT, exb, barId);
}

// ---------------- Phase A: layers 0-1 for 16 prefixes/batch ----------------
__global__ void __launch_bounds__(256)
qpie_phaseA(const float* __restrict__ x, const float* __restrict__ w,
            const float* __restrict__ pw, float* __restrict__ out, int out_n) {
    const int tid = threadIdx.x;
    const unsigned lane = tid & 31u;
    const int wib = tid >> 5;
    const int grp = wib >> 2;
    const int W   = wib & 3;
    const int w0 = W & 1, w1 = W >> 1;
    const int batch = blockIdx.x >> 3;
    const int pf = ((blockIdx.x & 7) << 1) | grp;   // 0..15
    const int c0 = pf & 3, c1 = (pf >> 2) & 3;
    const int barId = grp + 1;

    __shared__ float4 sM[2][16];
    __shared__ float  sCF[2][42];
    __shared__ float2 sT[2][64];
    __shared__ float2 sInit[8];
    __shared__ float  sPW[32];
    __shared__ float2 sEx[2][2][256];    // [grp][layer buf][slot*32+lane]
    __shared__ float4 sM2[16];
    __shared__ float  sCF2[42];

    // phase 1: base tables
    if (tid < 16) {
        int l = tid >> 3, q = tid & 7;
        make_tail(&sM[l][q*2], w + l*48, q, (l == 0) ? 1 : 2, x[batch*8 + q]);
    } else if (tid >= 32 && tid < 46) {
        int i = tid - 32, l = i / 7, p = i % 7;
        make_cf(&sCF[l][p*6], w + l*48 + 3*p);
    } else if (tid >= 64 && tid < 72) {
        int q = tid - 64;
        float s, c; sincosf(0.5f * x[batch*8 + q], &s, &c);
        sInit[q] = make_float2(c - s, c + s);
    } else if (tid >= 96 && tid < 128) {
        sPW[tid - 96] = pw[tid - 96];
    }
    if (blockIdx.x == 0) {
        if (tid >= 16 && tid < 32) g_PW2[tid - 16] = pw[32 + tid - 16];
        else if (tid >= 144 && tid < 152)
            make_tail(&sM2[(tid - 144)*2], w + 96, tid - 144, 0, 0.f);
        else if (tid >= 160 && tid < 167)
            make_cf(&sCF2[(tid - 160)*6], w + 96 + 3*(tid - 160));
        for (int i = tid; i < out_n; i += 256) out[i] = 0.f;
    }
    __syncthreads();

    // phase 2: build fused 8x8 tails
    if (tid < 64)       sT[0][tid]      = T_entry(tid,      sM[0], sCF[0]);
    else if (tid < 128) sT[1][tid - 64] = T_entry(tid - 64, sM[1], sCF[1]);
    if (blockIdx.x == 0) {
        if (tid >= 128 && tid < 192)      g_T2[tid - 128] = T_entry(tid - 128, sM2, sCF2);
        else if (tid >= 192 && tid < 202) g_M2[tid - 192] = sM2[tid - 192];
        else if (tid >= 208 && tid < 250) g_CF2[tid - 208] = sCF2[tid - 208];
    }
    __syncthreads();

    // initial product state (H then RY(x))|0>, real; 1/16 scale deferred
    float vre[2], vim[2];
    {
        float base = 1.f;
#pragma unroll
        for (int q = 0; q < 5; q++) base *= ((lane >> q) & 1u) ? sInit[q].y : sInit[q].x;
        base *= w0 ? sInit[6].y : sInit[6].x;
        base *= w1 ? sInit[7].y : sInit[7].x;
        vre[0] = base * sInit[5].x; vim[0] = 0.f;
        vre[1] = base * sInit[5].y; vim[1] = 0.f;
    }

    // layer 0 (even)
    branch_mul(vre, vim, &sPW[0], lane, w0, w1, c0 & 1, (c0 >> 1) & 1, true);
    layer_gates<true>(vre, vim, lane, W, c0 & 1, (c0 >> 1) & 1,
                      sCF[0], sM[0], sT[0], &sEx[grp][0][0], barId);
    // layer 1 (odd)
    branch_mul(vre, vim, &sPW[16], lane, w0, w1, c1 & 1, (c1 >> 1) & 1, false);
    layer_gates<true>(vre, vim, lane, W, c1 & 1, (c1 >> 1) & 1,
                      sCF[1], sM[1], sT[1], &sEx[grp][1][0], barId);

    const int base = ((batch*16 + pf) * 4 + W) * 64 + (int)lane;
    g_state[base]      = make_float2(vre[0], vim[0]);
    g_state[base + 32] = make_float2(vre[1], vim[1]);
}

// ---------------- Phase B: layer 2 + measurement, 64 paths/batch ----------------
__global__ void __launch_bounds__(128)
qpie_phaseB(float* __restrict__ out) {
    const int tid = threadIdx.x;
    const unsigned lane = tid & 31u;
    const int W = tid >> 5;
    const int w0 = W & 1, w1 = W >> 1;
    const int batch = blockIdx.x >> 6;
    const int path  = blockIdx.x & 63;
    const int pf = path & 15, c2 = path >> 4;
    const int r0 = c2 & 1, r1 = (c2 >> 1) & 1;

    __shared__ float2 sT[64];
    __shared__ float4 sM[10];
    __shared__ float  sCF[42];
    __shared__ float  sPW[16];
    __shared__ float2 sEx[256];
    __shared__ float  sOut[8];

    // flat copy of prebuilt tables (no trig)
    if (tid < 64) sT[tid] = g_T2[tid];
    if (tid < 42) sCF[tid] = g_CF2[tid];
    if (tid >= 64 && tid < 80) sPW[tid - 64] = g_PW2[tid - 64];
    if (tid >= 80 && tid < 90) sM[tid - 80] = g_M2[tid - 80];
    if (tid >= 96 && tid < 104) sOut[tid - 96] = 0.f;
    __syncthreads();

    // load prefix state
    float vre[2], vim[2];
    {
        const int base = ((batch*16 + pf) * 4 + W) * 64 + (int)lane;
        float2 v0 = g_state[base], v1 = g_state[base + 32];
        vre[0] = v0.x; vim[0] = v0.y;
        vre[1] = v1.x; vim[1] = v1.y;
    }
    // layer 2 (even)
    branch_mul(vre, vim, sPW, lane, w0, w1, r0, r1, true);
    layer_gates<false>(vre, vim, lane, W, r0, r1, sCF, sM, sT, sEx, 0);

    // ---- measurement: sign-tracking Walsh butterfly ----
    float p0 = vre[0]*vre[0] + vim[0]*vim[0];
    float p1 = vre[1]*vre[1] + vim[1]*vim[1];
    float A = p0 + p1, B = p0 - p1;
    float S[5];
#pragma unroll
    for (int k = 0; k < 5; k++) {
        const int mk = 1 << k;
        float Ap = __shfl_xor_sync(0xffffffffu, A, mk);
#pragma unroll
        for (int q = 0; q < 5; q++) {
            if (q < k) S[q] += __shfl_xor_sync(0xffffffffu, S[q], mk);
        }
        S[k] = ((lane >> k) & 1u) ? (Ap - A) : (A - Ap);
        A += Ap;
        B += __shfl_xor_sync(0xffffffffu, B, mk);
    }
    float v = S[0];
    if (lane == 1) v = S[1];
    else if (lane == 2) v = S[2];
    else if (lane == 3) v = S[3];
    else if (lane == 4) v = S[4];
    else if (lane == 5) v = B;
    else if (lane == 6) v = w0 ? -A : A;
    else if (lane == 7) v = w1 ? -A : A;
    if (lane < 8) atomicAdd(&sOut[lane], v);
    __syncthreads();
    if (tid < 8)
        atomicAdd(&out[batch*8 + tid], sOut[tid] * (1.f/256.f));
}

extern "C" void kernel_launch(void* const* d_in, const int* in_sizes, int n_in,
                              void* d_out, int out_size) {
    const float* x  = (const float*)d_in[0];   // [B, 8]
    const float* w  = (const float*)d_in[1];   // [3, 48]
    const float* pw = (const float*)d_in[2];   // [3, 2, 8]
    float* out = (float*)d_out;

    const int nb = in_sizes[0] / 8;            // 16
    qpie_phaseA<<<nb * 8,  256>>>(x, w, pw, out, out_size);
    qpie_phaseB<<<nb * 64, 128>>>(out);
}